// round 1
// baseline (speedup 1.0000x reference)
#include <cuda_runtime.h>
#include <math.h>

#define DD 256
#define HH 512
#define BB 128

// Pre-permuted, pre-masked weights in degree-sorted hidden order.
// net 0 = mu, net 1 = lv.
__device__ float g_W1s[2][HH * HH];   // [g_sorted][h_sorted], masked (deg(g)>=deg(h))
__device__ float g_W0sT[2][DD * HH];  // [j][h_sorted], masked (deg(h)>=j+1)
__device__ float g_Wos[2][DD * HH];   // [i][h_sorted], masked (i>=deg(h))
__device__ float g_b0s[2][HH];
__device__ float g_b1s[2][HH];

// sorted position -> original hidden unit.
// degrees: d(h) = (h % 255) + 1.  d=1: {0,255,510}, d=2: {1,256,511}, d>=3: {d-1, d+254}
__device__ __forceinline__ int permf(int p) {
    if (p < 3) return (p == 0) ? 0 : ((p == 1) ? 255 : 510);
    if (p < 6) { int q = p - 3; return (q == 0) ? 1 : ((q == 1) ? 256 : 511); }
    int d = 3 + ((p - 6) >> 1);
    return (((p - 6) & 1) == 0) ? (d - 1) : (d + 254);
}
__device__ __forceinline__ int degf(int p) {
    if (p < 3) return 1;
    if (p < 6) return 2;
    return 3 + ((p - 6) >> 1);
}
// P(i) = #units with degree <= i
__device__ __forceinline__ int Pfun(int i) {
    return (i <= 0) ? 0 : ((i == 1) ? 3 : (2 * i + 2));
}
__device__ __forceinline__ float eluf(float x) {
    return x > 0.f ? x : expm1f(x);
}
__device__ __forceinline__ float wredux(float v) {
#pragma unroll
    for (int o = 16; o; o >>= 1) v += __shfl_xor_sync(0xffffffffu, v, o);
    return v;
}

__global__ void setup_kernel(
    const float* __restrict__ W0m, const float* __restrict__ W1m, const float* __restrict__ Wom,
    const float* __restrict__ b0m, const float* __restrict__ b1m,
    const float* __restrict__ W0l, const float* __restrict__ W1l, const float* __restrict__ Wol,
    const float* __restrict__ b0l, const float* __restrict__ b1l)
{
    int tid = blockIdx.x * blockDim.x + threadIdx.x;
    int stride = gridDim.x * blockDim.x;

    for (int idx = tid; idx < HH * HH; idx += stride) {
        int g = idx >> 9, h = idx & 511;
        int pg = permf(g), ph = permf(h);
        float m = (degf(g) >= degf(h)) ? 1.f : 0.f;
        g_W1s[0][idx] = m * W1m[pg * HH + ph];
        g_W1s[1][idx] = m * W1l[pg * HH + ph];
    }
    for (int idx = tid; idx < DD * HH; idx += stride) {
        int j = idx >> 9, p = idx & 511;
        int pp = permf(p);
        int dp = degf(p);
        float m0 = (dp >= j + 1) ? 1.f : 0.f;
        g_W0sT[0][idx] = m0 * W0m[pp * DD + j];
        g_W0sT[1][idx] = m0 * W0l[pp * DD + j];
        float mo = (j >= dp) ? 1.f : 0.f;
        g_Wos[0][idx] = mo * Wom[j * HH + pp];
        g_Wos[1][idx] = mo * Wol[j * HH + pp];
    }
    for (int p = tid; p < HH; p += stride) {
        int pp = permf(p);
        g_b0s[0][p] = b0m[pp]; g_b0s[1][p] = b0l[pp];
        g_b1s[0][p] = b1m[pp]; g_b1s[1][p] = b1l[pp];
    }
}

// One CTA per batch element. 8 warps:
//   warps 0-2: layer-1 dots for newly-frozen units, mu net (slots 0..2)
//   warps 3-5: same, lv net
//   warp 6:    output dot (mu) over previously-frozen prefix
//   warp 7:    output dot (lv)
__global__ __launch_bounds__(256, 1) void made_kernel(
    const float* __restrict__ x,
    const float* __restrict__ bo_mu,
    const float* __restrict__ bo_lv,
    float* __restrict__ out)
{
    __shared__ float a0[2][HH], h0[2][HH], h1[2][HH];
    __shared__ float b0s[2][HH], b1s[2][HH];
    __shared__ float xs[DD], bos[2][DD];
    __shared__ float terms[6], partials[2];

    const int tid = threadIdx.x;
    const int b = blockIdx.x;
    const int w = tid >> 5, lane = tid & 31;

    for (int p = tid; p < HH; p += 256) {
        a0[0][p] = 0.f; a0[1][p] = 0.f;
        h0[0][p] = 0.f; h0[1][p] = 0.f;
        h1[0][p] = 0.f; h1[1][p] = 0.f;
        b0s[0][p] = g_b0s[0][p]; b0s[1][p] = g_b0s[1][p];
        b1s[0][p] = g_b1s[0][p]; b1s[1][p] = g_b1s[1][p];
    }
    for (int j = tid; j < DD; j += 256) {
        xs[j] = x[b * DD + j];
        bos[0][j] = bo_mu[j];
        bos[1][j] = bo_lv[j];
    }
    if (tid < 6) terms[tid] = 0.f;
    if (tid < 2) partials[tid] = 0.f;

    const bool isA1 = (w < 6);
    const int a1net = (w < 3) ? 0 : 1;
    const int slot = isA1 ? (w % 3) : -1;
    const int outnet = w - 6;

    float wrow[16];
#pragma unroll
    for (int r = 0; r < 16; r++) wrow[r] = 0.f;  // step 0: no new units, empty out-prefix
    float w0r[4];
    const int p0 = tid, p1 = tid + 256;
    w0r[0] = g_W0sT[0][p0];
    w0r[1] = g_W0sT[0][p1];
    w0r[2] = g_W0sT[1][p0];
    w0r[3] = g_W0sT[1][p1];
    float wos_sc = 0.f;

    float lvsum = 0.f;
    int Pprev = 0;

    for (int i = 0; i < DD; i++) {
        const int Pi = Pfun(i);
        const int newcount = Pi - Pprev;
        const int Pnext = (i + 1 < DD) ? Pfun(i + 1) : Pi;

        __syncthreads();  // publish a0/h0 updates from previous step

        if (isA1) {
            if (slot < newcount) {
                const int gpos = Pprev + slot;
                float acc = 0.f;
#pragma unroll
                for (int r = 0; r < 16; r++)
                    acc = fmaf(wrow[r], h0[a1net][r * 32 + lane], acc);
                acc = wredux(acc);
                if (lane == 0) {
                    float h1v = eluf(acc + b1s[a1net][gpos]);
                    h1[a1net][gpos] = h1v;
                    terms[w] = h1v * wos_sc;  // this unit's contribution to output col i
                }
            } else if (lane == 0) {
                terms[w] = 0.f;
            }
            // prefetch next step's W1s row (addresses are data-independent)
            const int nc_next = Pnext - Pi;
            if (slot < nc_next) {
                const int gnext = Pi + slot;
                const float* rowp = &g_W1s[a1net][gnext * HH];
#pragma unroll
                for (int r = 0; r < 16; r++) {
                    int p = r * 32 + lane;
                    wrow[r] = (p < Pnext) ? rowp[p] : 0.f;
                }
                if (lane == 0) wos_sc = g_Wos[a1net][(i + 1) * HH + gnext];
            }
        } else {
            // output dot over previously-frozen prefix (weights bounded at prefetch to < Pprev)
            float acc = 0.f;
#pragma unroll
            for (int r = 0; r < 16; r++)
                acc = fmaf(wrow[r], h1[outnet][r * 32 + lane], acc);
            acc = wredux(acc);
            if (lane == 0) partials[outnet] = acc;
            if (i + 1 < DD) {
                const float* rowp = &g_Wos[outnet][(i + 1) * HH];
#pragma unroll
                for (int r = 0; r < 16; r++) {
                    int p = r * 32 + lane;
                    wrow[r] = (p < Pi) ? rowp[p] : 0.f;  // next step's old-prefix bound
                }
            }
        }

        __syncthreads();  // publish h1/new terms/partials

        // all threads redundantly combine (avoids a third barrier)
        const float mu = partials[0] + terms[0] + terms[1] + terms[2] + bos[0][i];
        const float lvv = partials[1] + terms[3] + terms[4] + terms[5] + bos[1][i];
        const float logstd = 0.5f * lvv;
        const float ncol = (xs[i] - mu) / (expf(logstd) + 1e-12f);
        lvsum += logstd;
        if (tid == 0) out[b * DD + i] = ncol;

        // rank-1 layer-0 update (masked weights make non-suffix adds zero)
        a0[0][p0] = fmaf(ncol, w0r[0], a0[0][p0]);
        a0[0][p1] = fmaf(ncol, w0r[1], a0[0][p1]);
        a0[1][p0] = fmaf(ncol, w0r[2], a0[1][p0]);
        a0[1][p1] = fmaf(ncol, w0r[3], a0[1][p1]);

        // freeze h0 for units newly complete (needed at step i+1)
        if (p0 >= Pi && p0 < Pnext) {
            h0[0][p0] = eluf(a0[0][p0] + b0s[0][p0]);
            h0[1][p0] = eluf(a0[1][p0] + b0s[1][p0]);
        }
        if (p1 >= Pi && p1 < Pnext) {
            h0[0][p1] = eluf(a0[0][p1] + b0s[0][p1]);
            h0[1][p1] = eluf(a0[1][p1] + b0s[1][p1]);
        }

        // prefetch next step's W0sT row
        if (i + 1 < DD) {
            w0r[0] = g_W0sT[0][(i + 1) * HH + p0];
            w0r[1] = g_W0sT[0][(i + 1) * HH + p1];
            w0r[2] = g_W0sT[1][(i + 1) * HH + p0];
            w0r[3] = g_W0sT[1][(i + 1) * HH + p1];
        }

        Pprev = Pi;
    }

    if (tid == 0) out[BB * DD + b] = lvsum;
}

extern "C" void kernel_launch(void* const* d_in, const int* in_sizes, int n_in,
                              void* d_out, int out_size) {
    // inputs: 0:x 1:mu_W0 2:mu_b0 3:mu_W1 4:mu_b1 5:mu_Wo 6:mu_bo
    //         7:lv_W0 8:lv_b0 9:lv_W1 10:lv_b1 11:lv_Wo 12:lv_bo
    const float* xx    = (const float*)d_in[0];
    const float* muW0  = (const float*)d_in[1];
    const float* mub0  = (const float*)d_in[2];
    const float* muW1  = (const float*)d_in[3];
    const float* mub1  = (const float*)d_in[4];
    const float* muWo  = (const float*)d_in[5];
    const float* mubo  = (const float*)d_in[6];
    const float* lvW0  = (const float*)d_in[7];
    const float* lvb0  = (const float*)d_in[8];
    const float* lvW1  = (const float*)d_in[9];
    const float* lvb1  = (const float*)d_in[10];
    const float* lvWo  = (const float*)d_in[11];
    const float* lvbo  = (const float*)d_in[12];
    float* out = (float*)d_out;

    setup_kernel<<<512, 256>>>(muW0, muW1, muWo, mub0, mub1,
                               lvW0, lvW1, lvWo, lvb0, lvb1);
    made_kernel<<<BB, 256>>>(xx, mubo, lvbo, out);
}